// round 16
// baseline (speedup 1.0000x reference)
#include <cuda_runtime.h>
#include <cuda_fp16.h>
#include <math.h>

#define NB     2
#define SQ     2048
#define HIDDEN 1024
#define NHEAD  16
#define HDIM   64
#define SKVLEN 2048
#define TKV    4096
#define LOG2E  1.4426950408889634f

// half-precision staging buffers (pre-swizzled / tiled where noted)
__device__ __align__(1024) __half d_xh[NB * SQ * HIDDEN];      // [ks][m][64], SW128
__device__ __align__(1024) __half d_wh[3 * HIDDEN * HIDDEN];   // [z][ks][n][64], SW128
__device__ __align__(1024) __half d_kvsh[2 * NB * NHEAD * SKVLEN * HDIM]; // [2][bh][j][64], SW128
__device__ __align__(1024) __half d_qh[NB * NHEAD * SQ * HDIM];  // linear, pre-scaled log2e/64
__device__ __align__(1024) __half d_kh[NB * NHEAD * SQ * HDIM];  // [bh][s][64], SW128
__device__ __align__(1024) __half d_vh[NB * NHEAD * SQ * HDIM];  // [bh][s][64], SW128

// split-attention partial outputs
__device__ float d_o0[NB * NHEAD * SQ * HDIM];
__device__ float d_o1[NB * NHEAD * SQ * HDIM];
__device__ float d_l0[NB * NHEAD * SQ];
__device__ float d_l1[NB * NHEAD * SQ];

// ---------------------------------------------------------------------------
// helpers
// ---------------------------------------------------------------------------
__device__ __forceinline__ unsigned swz(unsigned b) { return b ^ ((b >> 3) & 0x70); }

__device__ __forceinline__ void mma16816(float c[4], unsigned a0, unsigned a1,
                                         unsigned a2, unsigned a3,
                                         unsigned b0, unsigned b1) {
    asm volatile(
        "mma.sync.aligned.m16n8k16.row.col.f32.f16.f16.f32 "
        "{%0,%1,%2,%3},{%4,%5,%6,%7},{%8,%9},{%0,%1,%2,%3};"
        : "+f"(c[0]), "+f"(c[1]), "+f"(c[2]), "+f"(c[3])
        : "r"(a0), "r"(a1), "r"(a2), "r"(a3), "r"(b0), "r"(b1));
}
__device__ __forceinline__ void mma16816h(unsigned c[2], unsigned a0, unsigned a1,
                                          unsigned a2, unsigned a3,
                                          unsigned b0, unsigned b1) {
    asm volatile(
        "mma.sync.aligned.m16n8k16.row.col.f16.f16.f16.f16 "
        "{%0,%1},{%2,%3,%4,%5},{%6,%7},{%0,%1};"
        : "+r"(c[0]), "+r"(c[1])
        : "r"(a0), "r"(a1), "r"(a2), "r"(a3), "r"(b0), "r"(b1));
}
__device__ __forceinline__ void ldsm_x4(unsigned& r0, unsigned& r1,
                                        unsigned& r2, unsigned& r3, unsigned a) {
    asm volatile("ldmatrix.sync.aligned.m8n8.x4.shared.b16 {%0,%1,%2,%3},[%4];"
                 : "=r"(r0), "=r"(r1), "=r"(r2), "=r"(r3) : "r"(a));
}
__device__ __forceinline__ void ldsm_x4t(unsigned& r0, unsigned& r1,
                                         unsigned& r2, unsigned& r3, unsigned a) {
    asm volatile("ldmatrix.sync.aligned.m8n8.x4.trans.shared.b16 {%0,%1,%2,%3},[%4];"
                 : "=r"(r0), "=r"(r1), "=r"(r2), "=r"(r3) : "r"(a));
}
__device__ __forceinline__ unsigned ex2h2(unsigned x) {
    unsigned r;
    asm("ex2.approx.f16x2 %0, %1;" : "=r"(r) : "r"(x));
    return r;
}
__device__ __forceinline__ void bulk_g2s(unsigned dst, const void* src,
                                         unsigned bytes, unsigned mbar) {
    asm volatile(
        "cp.async.bulk.shared::cluster.global.mbarrier::complete_tx::bytes "
        "[%0], [%1], %2, [%3];"
        :: "r"(dst), "l"(src), "r"(bytes), "r"(mbar) : "memory");
}
#define MBAR_INIT(mb, n) \
    asm volatile("mbarrier.init.shared.b64 [%0], %1;" :: "r"(mb), "r"((unsigned)(n)) : "memory")
#define MBAR_EXPECT_TX(mb, bytes) \
    asm volatile("mbarrier.arrive.expect_tx.shared.b64 _, [%0], %1;" \
                 :: "r"(mb), "r"((unsigned)(bytes)) : "memory")
#define MBAR_WAIT(mb, par) do { \
    unsigned _d; \
    asm volatile("{\n\t.reg .pred p;\n\t" \
        "mbarrier.try_wait.parity.acquire.cta.shared::cta.b64 p, [%1], %2;\n\t" \
        "selp.b32 %0, 1, 0, p;\n\t}" : "=r"(_d) : "r"(mb), "r"((unsigned)(par)) : "memory"); \
    if (!_d) { \
        asm volatile("{\n\t.reg .pred P1;\n\tWL_%=:\n\t" \
            "mbarrier.try_wait.parity.acquire.cta.shared::cta.b64 P1, [%0], %1, 0x989680;\n\t" \
            "@P1 bra.uni WD_%=;\n\tbra.uni WL_%=;\n\tWD_%=:\n\t}" \
            :: "r"(mb), "r"((unsigned)(par)) : "memory"); \
    } \
} while (0)

// ---------------------------------------------------------------------------
// Conversions.  Split: x+W (needed by projections) vs kvs (needed by attnA).
// ---------------------------------------------------------------------------
#define XN4   (NB * SQ * HIDDEN / 4)
#define WN4   (HIDDEN * HIDDEN / 4)
#define KVN4  (2 * NB * NHEAD * SKVLEN * HDIM / 4)
#define XWN4  (XN4 + 3 * WN4)

__global__ void cvt_xw_kernel(const float* __restrict__ x,
                              const float* __restrict__ Wq,
                              const float* __restrict__ Wk,
                              const float* __restrict__ Wv) {
    int j = blockIdx.x * blockDim.x + threadIdx.x;
    if (j >= XWN4) return;
    if (j < XN4) {
        float4 v = reinterpret_cast<const float4*>(x)[j];
        int m = j >> 8, k4 = (j & 255) * 4;
        unsigned hidx = (unsigned)(k4 >> 6) * (NB * SQ * 64u) + (unsigned)m * 64 + (k4 & 63);
        unsigned b = swz(hidx * 2);
        char* p = (char*)d_xh;
        *(__half2*)(p + b)     = __floats2half2_rn(v.x, v.y);
        *(__half2*)(p + b + 4) = __floats2half2_rn(v.z, v.w);
    } else {
        int jj = j - XN4;
        int z = jj / WN4;
        jj -= z * WN4;
        const float* W = (z == 0) ? Wq : (z == 1) ? Wk : Wv;
        float4 v = reinterpret_cast<const float4*>(W)[jj];
        int n = jj >> 8, k4 = (jj & 255) * 4;
        unsigned hidx = ((unsigned)(z * 16 + (k4 >> 6))) * 65536u + (unsigned)n * 64 + (k4 & 63);
        unsigned b = swz(hidx * 2);
        char* p = (char*)d_wh;
        *(__half2*)(p + b)     = __floats2half2_rn(v.x, v.y);
        *(__half2*)(p + b + 4) = __floats2half2_rn(v.z, v.w);
    }
}

__global__ void cvt_kvs_kernel(const float* __restrict__ kvs,
                               const float* __restrict__ kvw) {
    int j = blockIdx.x * blockDim.x + threadIdx.x;
    if (j >= KVN4) return;
    float s = kvw[0];
    float4 v = reinterpret_cast<const float4*>(kvs)[j];
    unsigned b = swz((unsigned)j * 8u);
    char* p = (char*)d_kvsh;
    *(__half2*)(p + b)     = __floats2half2_rn(v.x * s, v.y * s);
    *(__half2*)(p + b + 4) = __floats2half2_rn(v.z * s, v.w * s);
}

// ---------------------------------------------------------------------------
// QKV projection: y = x @ W^T + b.  fp16 mma, fp32 accum, bulk-copy staging.
// grid = (64, 8, nz), block = 128 (4 warps).  CTA tile m64 x n128 x k64 stage.
// 3-buffer mbarrier ring, issue at top of loop (2-stage prefetch depth).
// ---------------------------------------------------------------------------
#define QKV_STEP 24576
#define QKV_MB   (3 * QKV_STEP)
#define QKV_SMEM (QKV_MB + 24)

__global__ __launch_bounds__(128, 2)
void qkv_kernel(const float* __restrict__ bq, const float* __restrict__ bk,
                const float* __restrict__ bv, int zbase)
{
    extern __shared__ __align__(128) char sm[];

    const int z = zbase + blockIdx.z;
    const float* __restrict__ bias = (z == 0) ? bq : (z == 1) ? bk : bv;
    const float scl = (z == 0) ? (LOG2E / 64.0f) : 1.0f;

    const int m0 = blockIdx.x * 64;
    const int n0 = blockIdx.y * 128;
    const int tid = threadIdx.x, lane = tid & 31, w = tid >> 5;
    const int wm = w >> 1, wn = w & 1;
    const int l = lane;

    unsigned sbase;
    asm("{ .reg .u64 t; cvta.to.shared.u64 t, %1; cvt.u32.u64 %0, t; }" : "=r"(sbase) : "l"(sm));
    const unsigned mb = sbase + QKV_MB;

    auto issue = [&](int ks, int buf) {
        unsigned d = sbase + buf * QKV_STEP;
        unsigned m = mb + buf * 8;
        MBAR_EXPECT_TX(m, QKV_STEP);
        bulk_g2s(d,        d_xh + ((size_t)ks * (NB * SQ) + m0) * 64, 8192, m);
        bulk_g2s(d + 8192, d_wh + (((size_t)z * 16 + ks) * 1024 + n0) * 64, 16384, m);
    };

    if (tid == 0) { MBAR_INIT(mb, 1); MBAR_INIT(mb + 8, 1); MBAR_INIT(mb + 16, 1); }
    __syncthreads();
    if (tid == 0) { issue(0, 0); issue(1, 1); }

    const unsigned aB = (unsigned)(wm * 32 + (l & 15)) * 128 + (l >> 4) * 16;  // +2048 for m-block 1
    const unsigned bB = (unsigned)(wn * 64 + (l >> 4) * 8 + (l & 7)) * 128 + ((l >> 3) & 1) * 16;

    float acc[2][8][4] = {};

    for (int ks = 0; ks < 16; ks++) {
        int buf = ks - (ks / 3) * 3;
        MBAR_WAIT(mb + buf * 8, (ks / 3) & 1);
        // buffer (ks+2)%3 == (ks-1)%3 is free (its compute ended before the
        // end-of-(ks-1) __syncthreads); issue two stages ahead NOW.
        if (ks + 2 < 16 && tid == 0) {
            int b2 = (ks + 2) - ((ks + 2) / 3) * 3;
            issue(ks + 2, b2);
        }
        unsigned base = sbase + buf * QKV_STEP;

        #pragma unroll
        for (int kb = 0; kb < 4; kb++) {
            unsigned a0[4], a1[4];
            ldsm_x4(a0[0], a0[1], a0[2], a0[3], base + swz(aB + kb * 32));
            ldsm_x4(a1[0], a1[1], a1[2], a1[3], base + swz(aB + 2048 + kb * 32));
            #pragma unroll
            for (int nbp = 0; nbp < 4; nbp++) {
                unsigned b0, b1, b2, b3;
                ldsm_x4(b0, b1, b2, b3, base + 8192 + swz(bB + nbp * 2048 + kb * 32));
                mma16816(acc[0][nbp * 2],     a0[0], a0[1], a0[2], a0[3], b0, b1);
                mma16816(acc[0][nbp * 2 + 1], a0[0], a0[1], a0[2], a0[3], b2, b3);
                mma16816(acc[1][nbp * 2],     a1[0], a1[1], a1[2], a1[3], b0, b1);
                mma16816(acc[1][nbp * 2 + 1], a1[0], a1[1], a1[2], a1[3], b2, b3);
            }
        }
        __syncthreads();
    }

    const int h = blockIdx.y * 2 + wn;
    #pragma unroll
    for (int i = 0; i < 2; i++) {
        const int mlo = m0 + wm * 32 + i * 16 + (lane >> 2);
        #pragma unroll
        for (int nb = 0; nb < 8; nb++) {
            int dcol = nb * 8 + 2 * (lane & 3);
            float2 bv2 = *(const float2*)&bias[h * 64 + dcol];
            __half2 h0 = __floats2half2_rn((acc[i][nb][0] + bv2.x) * scl,
                                           (acc[i][nb][1] + bv2.y) * scl);
            __half2 h1 = __floats2half2_rn((acc[i][nb][2] + bv2.x) * scl,
                                           (acc[i][nb][3] + bv2.y) * scl);
            int m1 = mlo, m2 = mlo + 8;
            if (z == 0) {
                *(__half2*)&d_qh[(((size_t)(m1 >> 11) * NHEAD + h) * SQ + (m1 & 2047)) * HDIM + dcol] = h0;
                *(__half2*)&d_qh[(((size_t)(m2 >> 11) * NHEAD + h) * SQ + (m2 & 2047)) * HDIM + dcol] = h1;
            } else {
                char* p = (char*)((z == 1) ? d_kh : d_vh);
                unsigned i1 = (((unsigned)(m1 >> 11) * NHEAD + h) * SQ + (m1 & 2047)) * 64 + dcol;
                unsigned i2 = (((unsigned)(m2 >> 11) * NHEAD + h) * SQ + (m2 & 2047)) * 64 + dcol;
                *(__half2*)(p + swz(i1 * 2)) = h0;
                *(__half2*)(p + swz(i2 * 2)) = h1;
            }
        }
    }
}

// ---------------------------------------------------------------------------
// Flash attention (split): key stages [s0, s1) of 128 keys; bulk staging.
// grid = (16, 32), block = 128 (4 warps x m32 q-rows), q-tile 128.
// 3-buffer mbarrier ring, issue at top of loop.
// ---------------------------------------------------------------------------
#define AT_STEP  32768
#define AT_MB    (3 * AT_STEP)
#define ATTN_SMEM (AT_MB + 24)

__global__ __launch_bounds__(128, 2)
void attn_kernel(int s0, int s1, int part)
{
    extern __shared__ __align__(128) char sm[];

    const int tid = threadIdx.x, lane = tid & 31, w = tid >> 5;
    const int r0 = lane >> 2, m4 = lane & 3;
    const int wq = w * 32;
    const int q0 = blockIdx.x * 128;
    const int bh = blockIdx.y;
    const int l = lane;
    const int NS = s1 - s0;

    unsigned sbase;
    asm("{ .reg .u64 t; cvta.to.shared.u64 t, %1; cvt.u32.u64 %0, t; }" : "=r"(sbase) : "l"(sm));
    const unsigned mb = sbase + AT_MB;
    const unsigned ONES = 0x3C003C00u;

    // Q fragments, 2 m-blocks of 16 (linear layout, pre-scaled by log2e/64)
    unsigned qa[2][4][4];
    #pragma unroll
    for (int i = 0; i < 2; i++) {
        const __half* qb = d_qh + ((size_t)bh * SQ + q0 + wq + i * 16) * HDIM;
        #pragma unroll
        for (int kb = 0; kb < 4; kb++) {
            qa[i][kb][0] = *(const unsigned*)&qb[(r0    ) * 64 + kb * 16 + 2 * m4    ];
            qa[i][kb][1] = *(const unsigned*)&qb[(r0 + 8) * 64 + kb * 16 + 2 * m4    ];
            qa[i][kb][2] = *(const unsigned*)&qb[(r0    ) * 64 + kb * 16 + 2 * m4 + 8];
            qa[i][kb][3] = *(const unsigned*)&qb[(r0 + 8) * 64 + kb * 16 + 2 * m4 + 8];
        }
    }

    auto issue = [&](int st, int buf) {
        const __half *ks_p, *vs_p;
        if (st < 16) {
            ks_p = d_kvsh + ((size_t)bh * SKVLEN + st * 128) * 64;
            vs_p = d_kvsh + ((size_t)(NB * NHEAD + bh) * SKVLEN + st * 128) * 64;
        } else {
            int js = (st - 16) * 128;
            ks_p = d_kh + ((size_t)bh * SQ + js) * 64;
            vs_p = d_vh + ((size_t)bh * SQ + js) * 64;
        }
        unsigned d = sbase + buf * AT_STEP;
        unsigned m = mb + buf * 8;
        MBAR_EXPECT_TX(m, AT_STEP);
        bulk_g2s(d,         ks_p, 16384, m);
        bulk_g2s(d + 16384, vs_p, 16384, m);
    };

    if (tid == 0) { MBAR_INIT(mb, 1); MBAR_INIT(mb + 8, 1); MBAR_INIT(mb + 16, 1); }
    __syncthreads();
    if (tid == 0) { issue(s0, 0); issue(s0 + 1, 1); }

    const unsigned kB = (unsigned)((l >> 4) * 8 + (l & 7)) * 128 + ((l >> 3) & 1) * 16;
    const unsigned vB = (unsigned)(((l >> 3) & 1) * 8 + (l & 7)) * 128 + (l >> 4) * 16;

    float oacc[2][8][4] = {};
    float lacc[2][4] = {};

    for (int t = 0; t < NS; t++) {
        int buf = t - (t / 3) * 3;
        MBAR_WAIT(mb + buf * 8, (t / 3) & 1);
        if (t + 2 < NS && tid == 0) {
            int b2 = (t + 2) - ((t + 2) / 3) * 3;
            issue(s0 + t + 2, b2);
        }
        unsigned base = sbase + buf * AT_STEP;

        #pragma unroll
        for (int sub = 0; sub < 2; sub++) {
            unsigned so = sub * 8192;

            unsigned sc16[2][8][2];
            #pragma unroll
            for (int i = 0; i < 2; i++)
                #pragma unroll
                for (int nb = 0; nb < 8; nb++) { sc16[i][nb][0] = 0u; sc16[i][nb][1] = 0u; }
            #pragma unroll
            for (int kb = 0; kb < 4; kb++) {
                #pragma unroll
                for (int nbp = 0; nbp < 4; nbp++) {
                    unsigned b0, b1, b2, b3;
                    ldsm_x4(b0, b1, b2, b3, base + swz(kB + so + nbp * 2048 + kb * 32));
                    mma16816h(sc16[0][nbp * 2],     qa[0][kb][0], qa[0][kb][1], qa[0][kb][2], qa[0][kb][3], b0, b1);
                    mma16816h(sc16[0][nbp * 2 + 1], qa[0][kb][0], qa[0][kb][1], qa[0][kb][2], qa[0][kb][3], b2, b3);
                    mma16816h(sc16[1][nbp * 2],     qa[1][kb][0], qa[1][kb][1], qa[1][kb][2], qa[1][kb][3], b0, b1);
                    mma16816h(sc16[1][nbp * 2 + 1], qa[1][kb][0], qa[1][kb][1], qa[1][kb][2], qa[1][kb][3], b2, b3);
                }
            }

            unsigned pa[2][4][4];
            #pragma unroll
            for (int i = 0; i < 2; i++)
                #pragma unroll
                for (int kb = 0; kb < 4; kb++) {
                    pa[i][kb][0] = ex2h2(sc16[i][2 * kb][0]);
                    pa[i][kb][1] = ex2h2(sc16[i][2 * kb][1]);
                    pa[i][kb][2] = ex2h2(sc16[i][2 * kb + 1][0]);
                    pa[i][kb][3] = ex2h2(sc16[i][2 * kb + 1][1]);
                }

            #pragma unroll
            for (int kb = 0; kb < 4; kb++) {
                mma16816(lacc[0], pa[0][kb][0], pa[0][kb][1], pa[0][kb][2], pa[0][kb][3], ONES, ONES);
                mma16816(lacc[1], pa[1][kb][0], pa[1][kb][1], pa[1][kb][2], pa[1][kb][3], ONES, ONES);
                #pragma unroll
                for (int nbp = 0; nbp < 4; nbp++) {
                    unsigned b0, b1, b2, b3;
                    ldsm_x4t(b0, b1, b2, b3,
                             base + 16384 + swz(vB + so + kb * 2048 + nbp * 32));
                    mma16816(oacc[0][nbp * 2],     pa[0][kb][0], pa[0][kb][1], pa[0][kb][2], pa[0][kb][3], b0, b1);
                    mma16816(oacc[0][nbp * 2 + 1], pa[0][kb][0], pa[0][kb][1], pa[0][kb][2], pa[0][kb][3], b2, b3);
                    mma16816(oacc[1][nbp * 2],     pa[1][kb][0], pa[1][kb][1], pa[1][kb][2], pa[1][kb][3], b0, b1);
                    mma16816(oacc[1][nbp * 2 + 1], pa[1][kb][0], pa[1][kb][1], pa[1][kb][2], pa[1][kb][3], b2, b3);
                }
            }
        }
        __syncthreads();
    }

    // ---- partial epilogue ----
    float* op = part ? d_o1 : d_o0;
    float* lp = part ? d_l1 : d_l0;
    #pragma unroll
    for (int i = 0; i < 2; i++) {
        float* ob = op + ((size_t)bh * SQ + q0 + wq + i * 16) * HDIM;
        #pragma unroll
        for (int nb = 0; nb < 8; nb++) {
            float2 v0 = {oacc[i][nb][0], oacc[i][nb][1]};
            float2 v1 = {oacc[i][nb][2], oacc[i][nb][3]};
            *(float2*)&ob[(r0    ) * HDIM + nb * 8 + 2 * m4] = v0;
            *(float2*)&ob[(r0 + 8) * HDIM + nb * 8 + 2 * m4] = v1;
        }
        if (m4 == 0) {
            lp[bh * SQ + q0 + wq + i * 16 + r0]     = lacc[i][0];
            lp[bh * SQ + q0 + wq + i * 16 + r0 + 8] = lacc[i][2];
        }
    }
}

// ---------------------------------------------------------------------------
// Combine: out = (O0 + O1) / (l0 + l1), with [bh][q][d] -> [b][q][h*64+d]
// ---------------------------------------------------------------------------
__global__ void combine_kernel(float* __restrict__ out) {
    int i = blockIdx.x * blockDim.x + threadIdx.x;
    int d4 = i & 15;
    int q  = (i >> 4) & (SQ - 1);
    int bh = i >> 15;
    float4 a = ((const float4*)d_o0)[i];
    float4 b = ((const float4*)d_o1)[i];
    float inv = 1.0f / (d_l0[bh * SQ + q] + d_l1[bh * SQ + q]);
    float4 r;
    r.x = (a.x + b.x) * inv;
    r.y = (a.y + b.y) * inv;
    r.z = (a.z + b.z) * inv;
    r.w = (a.w + b.w) * inv;
    int bb = bh >> 4, h = bh & 15;
    ((float4*)out)[(size_t)(bb * SQ + q) * (HIDDEN / 4) + h * 16 + d4] = r;
}

// ---------------------------------------------------------------------------
extern "C" void kernel_launch(void* const* d_in, const int* in_sizes, int n_in,
                              void* d_out, int out_size)
{
    const float* x    = (const float*)d_in[0];
    const float* kvs  = (const float*)d_in[1];
    const float* Wq   = (const float*)d_in[2];
    const float* bq   = (const float*)d_in[3];
    const float* Wk   = (const float*)d_in[4];
    const float* bk   = (const float*)d_in[5];
    const float* Wv   = (const float*)d_in[6];
    const float* bv   = (const float*)d_in[7];
    const float* kvw  = (const float*)d_in[8];
    float* out = (float*)d_out;

    cudaFuncSetAttribute(qkv_kernel, cudaFuncAttributeMaxDynamicSharedMemorySize,
                         QKV_SMEM);
    cudaFuncSetAttribute(attn_kernel, cudaFuncAttributeMaxDynamicSharedMemorySize,
                         ATTN_SMEM);

    // ONE side stream (two streams tripped the teardown memory check in r14).
    cudaStream_t s2;
    cudaStreamCreateWithFlags(&s2, cudaStreamNonBlocking);
    cudaEvent_t evRoot, evXW, evQ, evKVS, evB;
    cudaEventCreateWithFlags(&evRoot, cudaEventDisableTiming);
    cudaEventCreateWithFlags(&evXW, cudaEventDisableTiming);
    cudaEventCreateWithFlags(&evQ, cudaEventDisableTiming);
    cudaEventCreateWithFlags(&evKVS, cudaEventDisableTiming);
    cudaEventCreateWithFlags(&evB, cudaEventDisableTiming);

    // Fork: s2 joins the capture graph via a root event BEFORE any launch.
    cudaEventRecord(evRoot, 0);
    cudaStreamWaitEvent(s2, evRoot, 0);

    // s2: kvs conversion (concurrent with cvt_xw) -> KV proj -> attnB
    cvt_kvs_kernel<<<(KVN4 + 255) / 256, 256, 0, s2>>>(kvs, kvw);
    cudaEventRecord(evKVS, s2);

    // s0: x+W conversion -> Q projection -> attnA (kvs keys; waits on evKVS)
    cvt_xw_kernel<<<(XWN4 + 255) / 256, 256>>>(x, Wq, Wk, Wv);
    cudaEventRecord(evXW, 0);

    dim3 gq(NB * SQ / 64, NHEAD / 2, 1);
    qkv_kernel<<<gq, 128, QKV_SMEM>>>(bq, bk, bv, 0);
    cudaEventRecord(evQ, 0);

    cudaStreamWaitEvent(0, evKVS, 0);
    dim3 g2(SQ / 128, NB * NHEAD);
    attn_kernel<<<g2, 128, ATTN_SMEM>>>(0, 16, 0);

    // s2 (cont.): K/V projection (needs x+W) -> attnB (needs Q too)
    cudaStreamWaitEvent(s2, evXW, 0);
    dim3 gkv(NB * SQ / 64, NHEAD / 2, 2);
    qkv_kernel<<<gkv, 128, QKV_SMEM, s2>>>(bq, bk, bv, 1);
    cudaStreamWaitEvent(s2, evQ, 0);
    attn_kernel<<<g2, 128, ATTN_SMEM, s2>>>(16, 32, 1);
    cudaEventRecord(evB, s2);

    // join and combine
    cudaStreamWaitEvent(0, evB, 0);
    combine_kernel<<<NB * NHEAD * SQ * HDIM / 4 / 256, 256>>>(out);
}